// round 8
// baseline (speedup 1.0000x reference)
#include <cuda_runtime.h>
#include <cstdint>

// ---------------------------------------------------------------------------
// MalConv via mma.sync IMMA s8 (m16n8k32), two-level int8 quantization.
//   E = sE*(128*eh + el),  W = sW*(128*wh + wl)
//   dot = sE*sW*(16384*acc_hh + 128*acc_mid),  acc_mid = eh*wl + el*wh
//   CTA: 128 patches x 64 interleaved cols (32 j), grid 125 mt x 4 nt = 500.
//   Chunk = 64 K (8 k-pos), NCHUNK = 63 (k>=500 zero padded).
// ---------------------------------------------------------------------------

#define NCHUNK   63
#define BATCH    8

// stage layout (bytes): Ahi 8K | Alo 8K | Bhi 4K | Blo 4K = 24 KB
#define AH_OFF   0
#define AL_OFF   8192
#define BH_OFF   16384
#define BL_OFF   20480
#define STG      24576
// after 2 stages (49152):
#define EMBH_OFF 49152          // uint2[257] int8x8
#define EMBL_OFF 51208
#define SMEM_TOTAL 53264

__device__ __align__(16) signed char g_B[NCHUNK * 32768]; // [c][hl][256n][64B]
__device__ int g_m[BATCH * 128];
__device__ int g_maxW;
__device__ int g_maxE;

// ---------------------------------------------------------------------------
__global__ void zero_kernel() {
    int i = blockIdx.x * 256 + threadIdx.x;
    if (i < BATCH * 128) g_m[i] = 0;
    if (i == 0) { g_maxW = 0; g_maxE = 0; }
}

__global__ void maxw_kernel(const float* __restrict__ W1,
                            const float* __restrict__ W2) {
    int i = blockIdx.x * 256 + threadIdx.x;
    float m = 0.f;
    for (int idx = i; idx < 1024000; idx += gridDim.x * 256) {
        float v = (idx < 512000) ? W1[idx] : W2[idx - 512000];
        m = fmaxf(m, fabsf(v));
    }
#pragma unroll
    for (int off = 16; off; off >>= 1)
        m = fmaxf(m, __shfl_xor_sync(0xFFFFFFFFu, m, off));
    if ((threadIdx.x & 31) == 0) atomicMax(&g_maxW, __float_as_int(m));
}

__global__ void maxe_kernel(const float* __restrict__ emb) {
    float m = 0.f;
    for (int idx = threadIdx.x; idx < 257 * 8; idx += 256)
        m = fmaxf(m, fabsf(emb[idx]));
#pragma unroll
    for (int off = 16; off; off >>= 1)
        m = fmaxf(m, __shfl_xor_sync(0xFFFFFFFFu, m, off));
    if ((threadIdx.x & 31) == 0) atomicMax(&g_maxE, __float_as_int(m));
}

// ---------------------------------------------------------------------------
__global__ void pack_kernel(const float* __restrict__ W1,
                            const float* __restrict__ W2) {
    int i = blockIdx.x * 256 + threadIdx.x;
    if (i >= NCHUNK * 2 * 256 * 64) return;
    int kk = i & 63;                 // byte within chunk row (kpl*8 + ch)
    int n  = (i >> 6) & 255;         // interleaved col
    int hl = (i >> 14) & 1;
    int c  = i >> 15;
    int K  = c * 64 + kk;
    int k  = K >> 3, ch = K & 7;
    float v = 0.f;
    if (k < 500) {
        int j = n >> 1;
        v = (n & 1) ? W2[j * 4000 + ch * 500 + k]
                    : W1[j * 4000 + ch * 500 + k];
    }
    float sw  = __int_as_float(g_maxW) * (1.f / 16256.f);
    float swh = sw * 128.f;
    float whf = rintf(v / swh);
    whf = fmaxf(-127.f, fminf(127.f, whf));
    float wlf = rintf((v - swh * whf) / sw);
    int quad = kk >> 4;
    size_t addr = (size_t)c * 32768 + hl * 16384 + n * 64
                + (((quad ^ (n & 3)) << 4) | (kk & 15));
    g_B[addr] = (signed char)(int)(hl ? wlf : whf);
}

// ---------------------------------------------------------------------------
__device__ __forceinline__ void cp_async16(uint32_t dst, const void* src) {
    asm volatile("cp.async.cg.shared.global [%0], [%1], 16;" :: "r"(dst), "l"(src));
}
__device__ __forceinline__ void cp_commit() { asm volatile("cp.async.commit_group;"); }
template <int N> __device__ __forceinline__ void cp_wait() {
    asm volatile("cp.async.wait_group %0;" :: "n"(N));
}
__device__ __forceinline__ void ldsm4(uint32_t a, uint32_t* r) {
    asm volatile("ldmatrix.sync.aligned.m8n8.x4.shared.b16 {%0,%1,%2,%3}, [%4];"
                 : "=r"(r[0]), "=r"(r[1]), "=r"(r[2]), "=r"(r[3]) : "r"(a));
}
__device__ __forceinline__ void imma(int* d, const uint32_t* a,
                                     uint32_t b0, uint32_t b1) {
    asm volatile(
        "mma.sync.aligned.m16n8k32.row.col.s32.s8.s8.s32 "
        "{%0,%1,%2,%3},{%4,%5,%6,%7},{%8,%9},{%0,%1,%2,%3};"
        : "+r"(d[0]), "+r"(d[1]), "+r"(d[2]), "+r"(d[3])
        : "r"(a[0]), "r"(a[1]), "r"(a[2]), "r"(a[3]), "r"(b0), "r"(b1));
}
__device__ __forceinline__ uint32_t swz64(int row, int quad) {
    return row * 64 + (((quad ^ (row & 3)) << 4));
}
__device__ __forceinline__ signed char q8(float v, float inv) {
    float r = rintf(v * inv);
    r = fmaxf(-127.f, fminf(127.f, r));
    return (signed char)(int)r;
}

// ---------------------------------------------------------------------------
__global__ void __launch_bounds__(256, 2)
malconv_kernel(const int* __restrict__ x, const float* __restrict__ emb,
               const float* __restrict__ b1, const float* __restrict__ b2) {
    extern __shared__ __align__(16) char smem[];
    const uint32_t sb = (uint32_t)__cvta_generic_to_shared(smem);
    const int tid  = threadIdx.x;
    const int lane = tid & 31;
    const int wid  = tid >> 5;
    const int wm   = wid >> 1;          // 0..3
    const int wn   = wid & 1;           // 0..1
    const int mt   = blockIdx.x >> 2;   // 0..124
    const int nt   = blockIdx.x & 3;    // 0..3

    const float sE  = __int_as_float(g_maxE) * (1.f / 16256.f);
    const float sEh = sE * 128.f;

    // int8 hi/lo embedding tables: uint2[257] each (8 channels -> 8 bytes)
    uint2* eH = (uint2*)(smem + EMBH_OFF);
    uint2* eL = (uint2*)(smem + EMBL_OFF);
    for (int i = tid; i < 257; i += 256) {
        const float* er = emb + i * 8;
        signed char h8[8], l8[8];
#pragma unroll
        for (int ch = 0; ch < 8; ch++) {
            float v = er[ch];
            float hh = rintf(v / sEh);
            hh = fmaxf(-127.f, fminf(127.f, hh));
            float ll = rintf((v - sEh * hh) / sE);
            h8[ch] = (signed char)(int)hh;
            l8[ch] = (signed char)(int)ll;
        }
        eH[i] = *(uint2*)h8;
        eL[i] = *(uint2*)l8;
    }

    int acch[2][4][4], accm[2][4][4];
#pragma unroll
    for (int a = 0; a < 2; a++)
#pragma unroll
        for (int b = 0; b < 4; b++)
#pragma unroll
            for (int q = 0; q < 4; q++) { acch[a][b][q] = 0; accm[a][b][q] = 0; }

    // builder: 2 threads per patch, each 4 k-pos (= 2 swizzle quads)
    const int bp  = tid >> 1;
    const int bk4 = (tid & 1) * 4;
    const int* xp = x + (size_t)(mt * 128 + bp) * 500 + bk4;

    auto build_A = [&](int buf, int4 xv, bool valid) {
        char* A = smem + buf * STG;
#pragma unroll
        for (int pp = 0; pp < 2; pp++) {
            int q = (tid & 1) * 2 + pp;
            uint32_t off = swz64(bp, q);
            uint4 vh = {0, 0, 0, 0}, vl = {0, 0, 0, 0};
            if (valid) {
                int v0 = pp ? xv.z : xv.x;
                int v1 = pp ? xv.w : xv.y;
                uint2 h0 = eH[v0], h1 = eH[v1];
                uint2 l0 = eL[v0], l1 = eL[v1];
                vh = make_uint4(h0.x, h0.y, h1.x, h1.y);
                vl = make_uint4(l0.x, l0.y, l1.x, l1.y);
            }
            *(uint4*)(A + AH_OFF + off) = vh;
            *(uint4*)(A + AL_OFF + off) = vl;
        }
    };
    auto load_B = [&](int c, int buf) {
        uint32_t d = sb + buf * STG + BH_OFF + tid * 16;
        const signed char* g = g_B + (size_t)c * 32768 + nt * 4096 + tid * 16;
        cp_async16(d, g);                    // hi slice (4 KB)
        cp_async16(d + 4096, g + 16384);     // lo slice
        cp_commit();
    };

    // ldmatrix lane-relative offsets (within a stage)
    uint32_t a_rel[2][2], b_rel[2][2];
#pragma unroll
    for (int ks = 0; ks < 2; ks++) {
#pragma unroll
        for (int fm = 0; fm < 2; fm++) {
            int row  = wm * 32 + fm * 16 + (lane & 15);
            int quad = 2 * ks + (lane >> 4);
            a_rel[ks][fm] = AH_OFF + swz64(row, quad);
        }
#pragma unroll
        for (int f2 = 0; f2 < 2; f2++) {
            int mat  = lane >> 3;
            int row  = wn * 32 + f2 * 16 + (mat >> 1) * 8 + (lane & 7);
            int quad = 2 * ks + (mat & 1);
            b_rel[ks][f2] = BH_OFF + swz64(row, quad);
        }
    }

    __syncthreads();                    // emb tables ready

    // prologue: chunk 0
    load_B(0, 0);
    build_A(0, *(const int4*)xp, true);
    int4 xv = *(const int4*)(xp + 8);   // chunk 1 (always valid)

    for (int it = 0; it < NCHUNK; ++it) {
        const int s = it & 1;
        __syncthreads();                // stage 1-s free
        if (it + 1 < NCHUNK) {
            load_B(it + 1, 1 - s);
            build_A(1 - s, xv, ((it + 1) * 8 + bk4) < 500);
            if (it + 2 < NCHUNK && ((it + 2) * 8 + bk4) < 500)
                xv = *(const int4*)(xp + (it + 2) * 8);
            cp_wait<1>();
        } else {
            cp_wait<0>();
        }
        __syncthreads();                // stage s visible

        const uint32_t stg = sb + s * STG;
#pragma unroll
        for (int ks = 0; ks < 2; ks++) {
            uint32_t ah[2][4], al[2][4];
            ldsm4(stg + a_rel[ks][0], ah[0]);
            ldsm4(stg + a_rel[ks][1], ah[1]);
            ldsm4(stg + a_rel[ks][0] + 8192, al[0]);
            ldsm4(stg + a_rel[ks][1] + 8192, al[1]);
#pragma unroll
            for (int f2 = 0; f2 < 2; f2++) {
                uint32_t bh[4], bl[4];
                ldsm4(stg + b_rel[ks][f2], bh);
                ldsm4(stg + b_rel[ks][f2] + 4096, bl);
#pragma unroll
                for (int fm = 0; fm < 2; fm++) {
#pragma unroll
                    for (int fb = 0; fb < 2; fb++) {
                        int* hh = acch[fm][f2 * 2 + fb];
                        int* md = accm[fm][f2 * 2 + fb];
                        imma(hh, ah[fm], bh[2 * fb], bh[2 * fb + 1]);
                        imma(md, ah[fm], bl[2 * fb], bl[2 * fb + 1]);
                        imma(md, al[fm], bh[2 * fb], bh[2 * fb + 1]);
                    }
                }
            }
        }
    }

    // ---- epilogue: scale + bias + GLU + relu + max over patches ----
    const float sW = __int_as_float(g_maxW) * (1.f / 16256.f);
    const float s2 = sE * sW;
    const int wbase = mt * 128 + wm * 32;
    const bool straddle = (wbase / 2000) != ((wbase + 31) / 2000);
#pragma unroll
    for (int fn = 0; fn < 4; fn++) {
        int j = nt * 32 + wn * 16 + fn * 4 + (lane & 3);
        float bb1 = b1[j], bb2 = b2[j];
        float h[2][2];
#pragma unroll
        for (int fm = 0; fm < 2; fm++) {
#pragma unroll
            for (int hf = 0; hf < 2; hf++) {
                float g1 = s2 * (16384.f * (float)acch[fm][fn][hf * 2 + 0]
                                 + 128.f * (float)accm[fm][fn][hf * 2 + 0]) + bb1;
                float g2 = s2 * (16384.f * (float)acch[fm][fn][hf * 2 + 1]
                                 + 128.f * (float)accm[fm][fn][hf * 2 + 1]) + bb2;
                h[fm][hf] = fmaxf(g1 * (1.f / (1.f + expf(-g2))), 0.f);
            }
        }
        if (!straddle) {
            float hm = fmaxf(fmaxf(h[0][0], h[0][1]), fmaxf(h[1][0], h[1][1]));
            hm = fmaxf(hm, __shfl_xor_sync(0xFFFFFFFFu, hm, 4));
            hm = fmaxf(hm, __shfl_xor_sync(0xFFFFFFFFu, hm, 8));
            hm = fmaxf(hm, __shfl_xor_sync(0xFFFFFFFFu, hm, 16));
            if ((lane >> 2) == 0)
                atomicMax(&g_m[(wbase / 2000) * 128 + j], __float_as_int(hm));
        } else {
#pragma unroll
            for (int fm = 0; fm < 2; fm++) {
#pragma unroll
                for (int hf = 0; hf < 2; hf++) {
                    int gp = wbase + fm * 16 + (lane >> 2) + hf * 8;
                    atomicMax(&g_m[(gp / 2000) * 128 + j],
                              __float_as_int(h[fm][hf]));
                }
            }
        }
    }
}

// ---------------------------------------------------------------------------
__global__ void fc_kernel(const float* __restrict__ fcW,
                          const float* __restrict__ fcb,
                          float* __restrict__ out) {
    int w    = threadIdx.x >> 5;
    int lane = threadIdx.x & 31;
    for (int pair = w; pair < BATCH * 2; pair += 8) {
        int b = pair >> 1;
        int j = pair & 1;
        float s = 0.f;
        for (int o = lane; o < 128; o += 32)
            s += __int_as_float(g_m[b * 128 + o]) * fcW[j * 128 + o];
#pragma unroll
        for (int off = 16; off; off >>= 1)
            s += __shfl_down_sync(0xFFFFFFFFu, s, off);
        if (lane == 0) out[b * 2 + j] = s + fcb[j];
    }
}

// ---------------------------------------------------------------------------
extern "C" void kernel_launch(void* const* d_in, const int* in_sizes, int n_in,
                              void* d_out, int out_size) {
    const int*   x   = (const int*)d_in[0];
    const float* emb = (const float*)d_in[1];
    const float* W1  = (const float*)d_in[2];
    const float* b1  = (const float*)d_in[3];
    const float* W2  = (const float*)d_in[4];
    const float* b2  = (const float*)d_in[5];
    const float* fcW = (const float*)d_in[6];
    const float* fcb = (const float*)d_in[7];
    float*       out = (float*)d_out;

    cudaFuncSetAttribute(malconv_kernel,
                         cudaFuncAttributeMaxDynamicSharedMemorySize, SMEM_TOTAL);

    zero_kernel<<<4, 256>>>();
    maxw_kernel<<<256, 256>>>(W1, W2);
    maxe_kernel<<<1, 256>>>(emb);
    pack_kernel<<<(NCHUNK * 2 * 256 * 64 + 255) / 256, 256>>>(W1, W2);
    malconv_kernel<<<500, 256, SMEM_TOTAL>>>(x, emb, b1, b2);
    fc_kernel<<<1, 256>>>(fcW, fcb, out);
}

// round 9
// speedup vs baseline: 6.8514x; 6.8514x over previous
#include <cuda_runtime.h>
#include <cuda_fp16.h>
#include <cstdint>

// ---------------------------------------------------------------------------
// MalConv via single-pass fp16 mma.sync (m16n8k16, f32 accumulate).
//   C[16000,256] = E[16000,4000] x W[4000,256], operands rounded to fp16
//   (e5m10, ~2^-11 rel) -> predicted output rel_err ~2-5e-4 < 1e-3.
//   Columns interleaved (g1_j, g2_j) so mma C-pairs = (g1, g2).
//   CTA: 128 patches x 128 cols, 8 warps (4m x 2n), warp tile 32x64.
//   K: 63 chunks of 64 (4032, zero-padded past 4000). Grid: 125 x 2 = 250.
// ---------------------------------------------------------------------------

#define NCHUNK   63
#define BATCH    8

// stage layout: A 128p x 64k fp16 (16 KB) | B 128n x 64k fp16 (16 KB)
#define A_OFF    0
#define B_OFF    16384
#define STG      32768
// after 2 stages:
#define EMB_OFF  65536          // uint4[257] fp16x8 rows
#define SMEM_TOTAL 69648

__device__ __align__(16) unsigned char g_B[NCHUNK * 32768]; // [c][256n][128B]
__device__ int g_m[BATCH * 128];

// ---------------------------------------------------------------------------
__global__ void zero_kernel() {
    int i = blockIdx.x * 256 + threadIdx.x;
    if (i < BATCH * 128) g_m[i] = 0;
}

// pack W into fp16, interleaved cols, 8-quad swizzled 128B rows, zero-pad tail
__global__ void pack_kernel(const float* __restrict__ W1,
                            const float* __restrict__ W2) {
    int i = blockIdx.x * 256 + threadIdx.x;
    if (i >= NCHUNK * 256 * 64) return;
    int kk = i & 63;                 // k within chunk
    int n  = (i >> 6) & 255;         // interleaved col: j = n>>1
    int c  = i >> 14;                // chunk
    int K  = c * 64 + kk;
    int k  = K >> 3, ch = K & 7;
    float v = 0.f;
    if (k < 500) {
        int j = n >> 1;
        v = (n & 1) ? W2[j * 4000 + ch * 500 + k]
                    : W1[j * 4000 + ch * 500 + k];
    }
    int quad = kk >> 3;              // 8 fp16 per 16B quad
    size_t addr = (size_t)c * 32768 + n * 128
                + (((quad ^ (n & 7)) << 4) | ((kk & 7) * 2));
    *(__half*)(g_B + addr) = __float2half(v);
}

// ---------------------------------------------------------------------------
__device__ __forceinline__ void cp_async16(uint32_t dst, const void* src) {
    asm volatile("cp.async.cg.shared.global [%0], [%1], 16;" :: "r"(dst), "l"(src));
}
__device__ __forceinline__ void cp_commit() { asm volatile("cp.async.commit_group;"); }
template <int N> __device__ __forceinline__ void cp_wait() {
    asm volatile("cp.async.wait_group %0;" :: "n"(N));
}
__device__ __forceinline__ void ldsm4(uint32_t a, uint32_t* r) {
    asm volatile("ldmatrix.sync.aligned.m8n8.x4.shared.b16 {%0,%1,%2,%3}, [%4];"
                 : "=r"(r[0]), "=r"(r[1]), "=r"(r[2]), "=r"(r[3]) : "r"(a));
}
__device__ __forceinline__ void mma16816(float* d, const uint32_t* a,
                                         uint32_t b0, uint32_t b1) {
    asm volatile(
        "mma.sync.aligned.m16n8k16.row.col.f32.f16.f16.f32 "
        "{%0,%1,%2,%3}, {%4,%5,%6,%7}, {%8,%9}, {%0,%1,%2,%3};"
        : "+f"(d[0]), "+f"(d[1]), "+f"(d[2]), "+f"(d[3])
        : "r"(a[0]), "r"(a[1]), "r"(a[2]), "r"(a[3]), "r"(b0), "r"(b1));
}
__device__ __forceinline__ uint32_t swz128(int row, int quad) {
    return row * 128 + (((quad ^ (row & 7)) << 4));
}

// ---------------------------------------------------------------------------
__global__ void __launch_bounds__(256, 2)
malconv_kernel(const int* __restrict__ x, const float* __restrict__ emb,
               const float* __restrict__ b1, const float* __restrict__ b2) {
    extern __shared__ __align__(16) char smem[];
    const uint32_t sb = (uint32_t)__cvta_generic_to_shared(smem);
    const int tid  = threadIdx.x;
    const int lane = tid & 31;
    const int wid  = tid >> 5;
    const int wm   = wid >> 1;          // 0..3  (m-warp)
    const int wn   = wid & 1;           // 0..1  (n-warp)
    const int mt   = blockIdx.x >> 1;   // 0..124
    const int nt   = blockIdx.x & 1;    // 0..1

    // fp16 embedding table: uint4[257] (8 channels = 16 B per row)
    uint4* eT = (uint4*)(smem + EMB_OFF);
    for (int i = tid; i < 257 * 8; i += 256)
        ((__half*)eT)[i] = __float2half(emb[i]);

    float acc[2][8][4];
#pragma unroll
    for (int a = 0; a < 2; a++)
#pragma unroll
        for (int b = 0; b < 8; b++)
#pragma unroll
            for (int q = 0; q < 4; q++) acc[a][b][q] = 0.f;

    // builder: 2 threads per patch, 4 k-pos (= 4 quads) each
    const int bp  = tid >> 1;
    const int bk4 = (tid & 1) * 4;
    const int* xp = x + (size_t)(mt * 128 + bp) * 500 + bk4;

    auto build_A = [&](int buf, int4 xv, bool valid) {
        char* A = smem + buf * STG + A_OFF;
#pragma unroll
        for (int pp = 0; pp < 4; pp++) {
            int q = bk4 + pp;
            uint4 v = {0, 0, 0, 0};
            if (valid) {
                int idx = (pp == 0) ? xv.x : (pp == 1) ? xv.y
                        : (pp == 2) ? xv.z : xv.w;
                v = eT[idx];
            }
            *(uint4*)(A + swz128(bp, q)) = v;
        }
    };
    auto load_B = [&](int c, int buf) {
        uint32_t d = sb + buf * STG + B_OFF + tid * 16;
        const unsigned char* g = g_B + (size_t)c * 32768 + nt * 16384 + tid * 16;
#pragma unroll
        for (int q = 0; q < 4; q++) cp_async16(d + q * 4096, g + q * 4096);
        cp_commit();
    };

    // ldmatrix lane-relative bases
    uint32_t arow[2], brow[4];
    int arx[2], brx[4];
    const int aq = lane >> 4;           // A quad select
    const int mat = lane >> 3;
    const int bq = mat & 1;             // B quad select
#pragma unroll
    for (int fm = 0; fm < 2; fm++) {
        int row = wm * 32 + fm * 16 + (lane & 15);
        arow[fm] = A_OFF + row * 128;
        arx[fm]  = row & 7;
    }
#pragma unroll
    for (int f2 = 0; f2 < 4; f2++) {
        int row = wn * 64 + f2 * 16 + (mat >> 1) * 8 + (lane & 7);
        brow[f2] = B_OFF + row * 128;
        brx[f2]  = row & 7;
    }

    __syncthreads();                    // emb table ready

    // prologue: chunk 0
    load_B(0, 0);
    build_A(0, *(const int4*)xp, true);
    int4 xv = *(const int4*)(xp + 8);   // chunk 1 (always valid: 8+bk4 < 500)

    for (int it = 0; it < NCHUNK; ++it) {
        const int s = it & 1;
        __syncthreads();                // stage 1-s free (prev compute done)
        if (it + 1 < NCHUNK) {
            load_B(it + 1, 1 - s);
            build_A(1 - s, xv, ((it + 1) * 8 + bk4) < 500);
            if (it + 2 < NCHUNK && ((it + 2) * 8 + bk4) < 500)
                xv = *(const int4*)(xp + (it + 2) * 8);
            cp_wait<1>();
        } else {
            cp_wait<0>();
        }
        __syncthreads();                // stage s visible

        const uint32_t stg = sb + s * STG;
#pragma unroll
        for (int ks = 0; ks < 4; ks++) {
            uint32_t ah[2][4];
#pragma unroll
            for (int fm = 0; fm < 2; fm++)
                ldsm4(stg + arow[fm] + (((2 * ks + aq) ^ arx[fm]) << 4), ah[fm]);
#pragma unroll
            for (int f2 = 0; f2 < 4; f2++) {
                uint32_t bh[4];
                ldsm4(stg + brow[f2] + (((2 * ks + bq) ^ brx[f2]) << 4), bh);
#pragma unroll
                for (int fm = 0; fm < 2; fm++) {
#pragma unroll
                    for (int fb = 0; fb < 2; fb++)
                        mma16816(acc[fm][f2 * 2 + fb], ah[fm],
                                 bh[2 * fb], bh[2 * fb + 1]);
                }
            }
        }
    }

    // ---- epilogue: bias + GLU + relu + max over patches ----
    const int wbase = mt * 128 + wm * 32;
    const bool straddle = (wbase / 2000) != ((wbase + 31) / 2000);
#pragma unroll
    for (int fn = 0; fn < 8; fn++) {
        int j = nt * 64 + wn * 32 + fn * 4 + (lane & 3);
        float bb1 = b1[j], bb2 = b2[j];
        float h[2][2];
#pragma unroll
        for (int fm = 0; fm < 2; fm++) {
#pragma unroll
            for (int hf = 0; hf < 2; hf++) {
                float g1 = acc[fm][fn][hf * 2 + 0] + bb1;
                float g2 = acc[fm][fn][hf * 2 + 1] + bb2;
                h[fm][hf] = fmaxf(g1 * (1.f / (1.f + expf(-g2))), 0.f);
            }
        }
        if (!straddle) {
            float hm = fmaxf(fmaxf(h[0][0], h[0][1]), fmaxf(h[1][0], h[1][1]));
            hm = fmaxf(hm, __shfl_xor_sync(0xFFFFFFFFu, hm, 4));
            hm = fmaxf(hm, __shfl_xor_sync(0xFFFFFFFFu, hm, 8));
            hm = fmaxf(hm, __shfl_xor_sync(0xFFFFFFFFu, hm, 16));
            if ((lane >> 2) == 0)
                atomicMax(&g_m[(wbase / 2000) * 128 + j], __float_as_int(hm));
        } else {
#pragma unroll
            for (int fm = 0; fm < 2; fm++) {
#pragma unroll
                for (int hf = 0; hf < 2; hf++) {
                    int gp = wbase + fm * 16 + (lane >> 2) + hf * 8;
                    atomicMax(&g_m[(gp / 2000) * 128 + j],
                              __float_as_int(h[fm][hf]));
                }
            }
        }
    }
}

// ---------------------------------------------------------------------------
__global__ void fc_kernel(const float* __restrict__ fcW,
                          const float* __restrict__ fcb,
                          float* __restrict__ out) {
    int w    = threadIdx.x >> 5;
    int lane = threadIdx.x & 31;
    for (int pair = w; pair < BATCH * 2; pair += 8) {
        int b = pair >> 1;
        int j = pair & 1;
        float s = 0.f;
        for (int o = lane; o < 128; o += 32)
            s += __int_as_float(g_m[b * 128 + o]) * fcW[j * 128 + o];
#pragma unroll
        for (int off = 16; off; off >>= 1)
            s += __shfl_down_sync(0xFFFFFFFFu, s, off);
        if (lane == 0) out[b * 2 + j] = s + fcb[j];
    }
}

// ---------------------------------------------------------------------------
extern "C" void kernel_launch(void* const* d_in, const int* in_sizes, int n_in,
                              void* d_out, int out_size) {
    const int*   x   = (const int*)d_in[0];
    const float* emb = (const float*)d_in[1];
    const float* W1  = (const float*)d_in[2];
    const float* b1  = (const float*)d_in[3];
    const float* W2  = (const float*)d_in[4];
    const float* b2  = (const float*)d_in[5];
    const float* fcW = (const float*)d_in[6];
    const float* fcb = (const float*)d_in[7];
    float*       out = (float*)d_out;

    cudaFuncSetAttribute(malconv_kernel,
                         cudaFuncAttributeMaxDynamicSharedMemorySize, SMEM_TOTAL);

    zero_kernel<<<4, 256>>>();
    pack_kernel<<<(NCHUNK * 256 * 64 + 255) / 256, 256>>>(W1, W2);
    malconv_kernel<<<250, 256, SMEM_TOTAL>>>(x, emb, b1, b2);
    fc_kernel<<<1, 256>>>(fcW, fcb, out);
}